// round 7
// baseline (speedup 1.0000x reference)
#include <cuda_runtime.h>
#include <math.h>

#define D        128
#define K_NEG    4
#define T        8          // same-relation triples per score block
#define NVEC     (5 * T)    // u-vectors per block
#define MAX_M    16384
#define MAX_REL  256
#define NPAD_MAX (MAX_M + MAX_REL * T)

// packed f32x2 FMA: d = a*b + c elementwise on two packed floats (Blackwell FFMA2)
#define FMA_F32X2(d, a, b, c) \
    asm("fma.rn.f32x2 %0, %1, %2, %3;" : "=l"(d) : "l"(a), "l"(b), "l"(c))
#define UNPACK_F32X2(lo, hi, in) \
    asm("mov.b64 {%0, %1}, %2;" : "=f"(lo), "=f"(hi) : "l"(in))

// ---- allocation-free scratch (__device__ globals) ----
__device__ float g_loss[MAX_M];
__device__ int   g_order[NPAD_MAX];

// K0: fused prologue, ONE block. Poison order array, smem histogram by
// relation, padded exclusive scan, scatter. All counters in smem.
__global__ void __launch_bounds__(1024) kg_prologue_kernel(
    const int* __restrict__ rel_ids, int M, int n_rel, int npad)
{
    __shared__ int scnt[MAX_REL];
    __shared__ int soff[MAX_REL];
    __shared__ int spos[MAX_REL];
    const int tid = threadIdx.x;

    for (int i = tid; i < npad; i += 1024) g_order[i] = -1;
    for (int i = tid; i < n_rel; i += 1024) { scnt[i] = 0; spos[i] = 0; }
    __syncthreads();

    for (int m = tid; m < M; m += 1024) atomicAdd(&scnt[rel_ids[m]], 1);
    __syncthreads();

    if (tid == 0) {
        int acc = 0;
        for (int r = 0; r < n_rel; r++) {
            soff[r] = acc;
            acc += ((scnt[r] + T - 1) / T) * T;
        }
    }
    __syncthreads();

    for (int m = tid; m < M; m += 1024) {
        const int r = rel_ids[m];
        const int p = atomicAdd(&spos[r], 1);
        g_order[soff[r] + p] = m;
    }
}

// K1: score. One block per T-slot same-relation tile; each thread owns one
// R row, streamed once and amortized over 5*T dot products computed with
// packed fma.rn.f32x2 (even/odd dim pairs packed in 64-bit accumulators).
// score_j = || R*(h - t_j) + e ||^2.
__global__ void __launch_bounds__(128, 4) kg_score_kernel(
    const float* __restrict__ mol_emb,        // [B, D]
    const float* __restrict__ entity_emb,     // [N_ENT, D]
    const float* __restrict__ relation_emb,   // [N_REL, D]
    const float* __restrict__ relation_matrix,// [N_REL, D, D]
    const int*   __restrict__ tail_ids,       // [M]
    const int*   __restrict__ rel_ids,        // [M]
    const int*   __restrict__ neg_indices,    // [M, K]
    int n_per_b)
{
    __shared__ __align__(16) float u[NVEC][D];   // 20 KB
    __shared__ float evec[D];
    __shared__ float red[4][NVEC];
    __shared__ int   sm_m[T];
    __shared__ int   sm_b[T];
    __shared__ int   sm_row[NVEC];
    __shared__ int   sm_rel;

    const int tid = threadIdx.x;

    if (tid < T) {
        const int m = g_order[blockIdx.x * T + tid];
        sm_m[tid] = m;
        sm_b[tid] = (m >= 0) ? (m / n_per_b) : -1;
    }
    __syncthreads();

    // stage gather indices once (not 128x redundantly)
    if (tid < NVEC) {
        const int i = tid / 5, q = tid - i * 5;
        const int m = sm_m[i];
        int row = -1;
        if (m >= 0)
            row = (q == 0) ? tail_ids[m]
                           : tail_ids[neg_indices[m * K_NEG + (q - 1)]];
        sm_row[tid] = row;
        if (tid == 0) {
            int r = -1;
            #pragma unroll
            for (int j = 0; j < T; j++)
                if (r < 0 && sm_m[j] >= 0) r = rel_ids[sm_m[j]];
            sm_rel = r;
        }
    }
    __syncthreads();

    const int r_id = sm_rel;
    if (r_id < 0) return;            // dead padding block (uniform exit)

    // ---- setup: u vectors + e in smem; thread c owns column c ----
    {
        const int c = tid;
        evec[c] = relation_emb[(size_t)r_id * D + c];
        #pragma unroll
        for (int i = 0; i < T; i++) {
            const int b = sm_b[i];
            const float h = (b >= 0) ? mol_emb[(size_t)b * D + c] : 0.f;
            #pragma unroll
            for (int q = 0; q < 5; q++) {
                const int row = sm_row[i * 5 + q];
                u[i * 5 + q][c] =
                    (row >= 0) ? (h - entity_emb[(size_t)row * D + c]) : 0.f;
            }
        }
    }
    __syncthreads();

    // ---- 40 packed dot products of R row `tid` against u[0..39] ----
    // ulonglong2 view: .x = dims (4c, 4c+1), .y = dims (4c+2, 4c+3)
    const ulonglong2* __restrict__ Rrow2 =
        reinterpret_cast<const ulonglong2*>(
            relation_matrix + ((size_t)r_id * D + tid) * D);
    const ulonglong2* __restrict__ u2 =
        reinterpret_cast<const ulonglong2*>(u);

    unsigned long long acc[NVEC];
    #pragma unroll
    for (int j = 0; j < NVEC; j++) acc[j] = 0ull;

    #pragma unroll 2
    for (int c4 = 0; c4 < D / 4; c4++) {         // 4 dims (2 pairs) per iter
        const ulonglong2 r2 = Rrow2[c4];
        #pragma unroll
        for (int j = 0; j < NVEC; j++) {
            const ulonglong2 v2 = u2[j * (D / 4) + c4];  // broadcast LDS.128
            FMA_F32X2(acc[j], r2.x, v2.x, acc[j]);
            FMA_F32X2(acc[j], r2.y, v2.y, acc[j]);
        }
    }

    // ---- (dot + e_row)^2, reduce over 128 rows ----
    const float e = evec[tid];
    const int warp = tid >> 5;
    const int lane = tid & 31;
    #pragma unroll
    for (int j = 0; j < NVEC; j++) {
        float lo, hi;
        UNPACK_F32X2(lo, hi, acc[j]);
        float s = (lo + hi) + e;
        s *= s;
        #pragma unroll
        for (int off = 16; off > 0; off >>= 1)
            s += __shfl_down_sync(0xFFFFFFFFu, s, off);
        if (lane == 0) red[warp][j] = s;
    }
    __syncthreads();

    if (tid < T) {
        const int m = sm_m[tid];
        if (m >= 0) {
            float sc[5];
            #pragma unroll
            for (int q = 0; q < 5; q++)
                sc[q] = red[0][tid * 5 + q] + red[1][tid * 5 + q] +
                        red[2][tid * 5 + q] + red[3][tid * 5 + q];
            const float neg_mean = (sc[1] + sc[2] + sc[3] + sc[4]) * 0.25f;
            const float x = neg_mean - sc[0];
            const float sig = 1.0f / (1.0f + expf(-x));  // -inf -> 0, ref-compatible
            g_loss[m] = -logf(sig + 1e-12f);
        }
    }
}

// K2: deterministic single-block tree reduce: out = (sum_m loss_m) / B.
__global__ void __launch_bounds__(1024) kg_reduce_kernel(
    float* __restrict__ out, int M, float invB)
{
    __shared__ float s[1024];
    const float4* __restrict__ g4 = reinterpret_cast<const float4*>(g_loss);
    const int n4 = M >> 2;
    float sum = 0.f;
    for (int i = threadIdx.x; i < n4; i += 1024) {
        const float4 v = g4[i];
        sum += (v.x + v.y) + (v.z + v.w);
    }
    s[threadIdx.x] = sum;
    __syncthreads();
    #pragma unroll
    for (int st = 512; st > 0; st >>= 1) {
        if (threadIdx.x < st) s[threadIdx.x] += s[threadIdx.x + st];
        __syncthreads();
    }
    if (threadIdx.x == 0) out[0] = s[0] * invB;
}

extern "C" void kernel_launch(void* const* d_in, const int* in_sizes, int n_in,
                              void* d_out, int out_size)
{
    const float* mol_emb         = (const float*)d_in[0];
    const float* entity_emb      = (const float*)d_in[1];
    const float* relation_emb    = (const float*)d_in[2];
    const float* relation_matrix = (const float*)d_in[3];
    const int*   tail_ids        = (const int*)d_in[4];
    const int*   rel_ids         = (const int*)d_in[5];
    const int*   neg_indices     = (const int*)d_in[6];
    float* out = (float*)d_out;

    const int B = in_sizes[0] / D;                 // 512
    int n_rel = in_sizes[2] / D;                   // 64
    if (n_rel > MAX_REL) n_rel = MAX_REL;
    int M = in_sizes[5];                           // 8192
    if (M > MAX_M) M = MAX_M;
    const int n_per_b = M / B;                     // 16

    const int NB   = M / T + n_rel;                // padded tile upper bound
    const int npad = NB * T;

    kg_prologue_kernel<<<1, 1024>>>(rel_ids, M, n_rel, npad);
    kg_score_kernel<<<NB, 128>>>(mol_emb, entity_emb, relation_emb,
                                 relation_matrix, tail_ids, rel_ids,
                                 neg_indices, n_per_b);
    kg_reduce_kernel<<<1, 1024>>>(out, M, 1.0f / (float)B);
}

// round 10
// speedup vs baseline: 1.0764x; 1.0764x over previous
#include <cuda_runtime.h>
#include <math.h>

#define D        128
#define K_NEG    4
#define T        4          // same-relation triples per score block
#define NVEC     (5 * T)    // u-vectors per block (=20)
#define MAX_M    16384
#define MAX_REL  256
#define NPAD_MAX (MAX_M + MAX_REL * T)

// packed f32x2 FMA: d = a*b + c elementwise on two packed floats
#define FMA_F32X2(d, a, b, c) \
    asm("fma.rn.f32x2 %0, %1, %2, %3;" : "=l"(d) : "l"(a), "l"(b), "l"(c))
#define UNPACK_F32X2(lo, hi, in) \
    asm("mov.b64 {%0, %1}, %2;" : "=f"(lo), "=f"(hi) : "l"(in))

// ---- allocation-free scratch ----
__device__ int g_order[NPAD_MAX];

// K0: fused prologue, ONE block: zero out[0], smem histogram by relation,
// warp-parallel padded exclusive scan, then scatter + pad-fill + tail
// poison (only unwritten slots are poisoned; no full-array poison pass).
// Invariant: every replay rewrites ALL npad slots the score kernel reads.
__global__ void __launch_bounds__(1024) kg_prologue_kernel(
    const int* __restrict__ rel_ids, float* __restrict__ out,
    int M, int n_rel, int npad)
{
    __shared__ int scnt[MAX_REL];
    __shared__ int soff[MAX_REL];
    __shared__ int spos[MAX_REL];
    __shared__ int stotal;
    const int tid = threadIdx.x;

    if (tid == 0) out[0] = 0.0f;
    for (int i = tid; i < n_rel; i += 1024) { scnt[i] = 0; spos[i] = 0; }
    __syncthreads();

    for (int m = tid; m < M; m += 1024) atomicAdd(&scnt[rel_ids[m]], 1);
    __syncthreads();

    // padded exclusive scan of bucket sizes (n_rel <= 64 fast path)
    if (n_rel <= 64) {
        if (tid < 32) {
            const int lane = tid;
            const int p0 = (lane < n_rel)
                ? ((scnt[lane] + T - 1) / T) * T : 0;
            const int p1 = (lane + 32 < n_rel)
                ? ((scnt[lane + 32] + T - 1) / T) * T : 0;
            int c0 = p0, c1 = p1;
            #pragma unroll
            for (int off = 1; off < 32; off <<= 1) {
                int n0 = __shfl_up_sync(0xFFFFFFFFu, c0, off);
                int n1 = __shfl_up_sync(0xFFFFFFFFu, c1, off);
                if (lane >= off) { c0 += n0; c1 += n1; }
            }
            const int tot0 = __shfl_sync(0xFFFFFFFFu, c0, 31);
            const int tot1 = __shfl_sync(0xFFFFFFFFu, c1, 31);
            if (lane < n_rel) soff[lane] = c0 - p0;
            if (lane + 32 < n_rel) soff[lane + 32] = tot0 + c1 - p1;
            if (lane == 31) stotal = tot0 + tot1;
        }
    } else if (tid == 0) {
        int acc = 0;
        for (int r = 0; r < n_rel; r++) {
            soff[r] = acc;
            acc += ((scnt[r] + T - 1) / T) * T;
        }
        stotal = acc;
    }
    __syncthreads();

    // scatter real triples
    for (int m = tid; m < M; m += 1024) {
        const int r = rel_ids[m];
        const int p = atomicAdd(&spos[r], 1);
        g_order[soff[r] + p] = m;
    }
    // per-bucket pad slots (< T-1 per relation)
    {
        const int r = tid / T, s = tid % T;     // covers n_rel*T <= 1024 for n_rel<=256? no: only first 1024/T rels
        for (int rr = r; rr < n_rel; rr += 1024 / T) {
            const int cnt = scnt[rr];
            const int pad = ((cnt + T - 1) / T) * T;
            const int slot = cnt + s;
            if (slot < pad) g_order[soff[rr] + slot] = -1;
        }
    }
    // tail poison [stotal, npad)
    for (int i = stotal + tid; i < npad; i += 1024) g_order[i] = -1;
}

// K1: score. One block per T-slot same-relation tile; each thread owns one
// R row (LDG once, amortized over 5*T dot products) computed with packed
// fma.rn.f32x2. score_j = || R*(h - t_j) + e ||^2. Block's loss sum is
// atomically accumulated into out[0] (order-only nondeterminism ~1e-7).
__global__ void __launch_bounds__(128) kg_score_kernel(
    const float* __restrict__ mol_emb,        // [B, D]
    const float* __restrict__ entity_emb,     // [N_ENT, D]
    const float* __restrict__ relation_emb,   // [N_REL, D]
    const float* __restrict__ relation_matrix,// [N_REL, D, D]
    const int*   __restrict__ tail_ids,       // [M]
    const int*   __restrict__ rel_ids,        // [M]
    const int*   __restrict__ neg_indices,    // [M, K]
    float* __restrict__ out,
    int n_per_b, float invB)
{
    __shared__ __align__(16) float u[NVEC][D];   // 10 KB
    __shared__ float evec[D];
    __shared__ float red[4][NVEC];
    __shared__ float lsum[T];
    __shared__ int   sm_m[T];
    __shared__ int   sm_b[T];
    __shared__ int   sm_row[NVEC];
    __shared__ int   sm_rel;

    const int tid = threadIdx.x;

    if (tid < T) {
        const int m = g_order[blockIdx.x * T + tid];
        sm_m[tid] = m;
        sm_b[tid] = (m >= 0) ? (m / n_per_b) : -1;
    }
    __syncthreads();

    // stage gather indices once
    if (tid < NVEC) {
        const int i = tid / 5, q = tid - i * 5;
        const int m = sm_m[i];
        int row = -1;
        if (m >= 0)
            row = (q == 0) ? tail_ids[m]
                           : tail_ids[neg_indices[m * K_NEG + (q - 1)]];
        sm_row[tid] = row;
        if (tid == 0) {
            int r = -1;
            #pragma unroll
            for (int j = 0; j < T; j++)
                if (r < 0 && sm_m[j] >= 0) r = rel_ids[sm_m[j]];
            sm_rel = r;
        }
    }
    __syncthreads();

    const int r_id = sm_rel;
    if (r_id < 0) return;            // dead padding block (uniform exit)

    // ---- setup: u vectors + e in smem; thread c owns column c ----
    {
        const int c = tid;
        evec[c] = relation_emb[(size_t)r_id * D + c];
        #pragma unroll
        for (int i = 0; i < T; i++) {
            const int b = sm_b[i];
            const float h = (b >= 0) ? mol_emb[(size_t)b * D + c] : 0.f;
            #pragma unroll
            for (int q = 0; q < 5; q++) {
                const int row = sm_row[i * 5 + q];
                u[i * 5 + q][c] =
                    (row >= 0) ? (h - entity_emb[(size_t)row * D + c]) : 0.f;
            }
        }
    }
    __syncthreads();

    // ---- 20 packed dot products of R row `tid` against u[0..19] ----
    const ulonglong2* __restrict__ Rrow2 =
        reinterpret_cast<const ulonglong2*>(
            relation_matrix + ((size_t)r_id * D + tid) * D);
    const ulonglong2* __restrict__ u2 =
        reinterpret_cast<const ulonglong2*>(u);

    unsigned long long acc[NVEC];
    #pragma unroll
    for (int j = 0; j < NVEC; j++) acc[j] = 0ull;

    #pragma unroll 2
    for (int c4 = 0; c4 < D / 4; c4++) {         // 4 dims (2 pairs) per iter
        const ulonglong2 r2 = Rrow2[c4];
        #pragma unroll
        for (int j = 0; j < NVEC; j++) {
            const ulonglong2 v2 = u2[j * (D / 4) + c4];  // broadcast LDS.128
            FMA_F32X2(acc[j], r2.x, v2.x, acc[j]);
            FMA_F32X2(acc[j], r2.y, v2.y, acc[j]);
        }
    }

    // ---- (dot + e_row)^2, reduce over 128 rows ----
    const float e = evec[tid];
    const int warp = tid >> 5;
    const int lane = tid & 31;
    #pragma unroll
    for (int j = 0; j < NVEC; j++) {
        float lo, hi;
        UNPACK_F32X2(lo, hi, acc[j]);
        float s = (lo + hi) + e;
        s *= s;
        #pragma unroll
        for (int off = 16; off > 0; off >>= 1)
            s += __shfl_down_sync(0xFFFFFFFFu, s, off);
        if (lane == 0) red[warp][j] = s;
    }
    __syncthreads();

    if (tid < T) {
        const int m = sm_m[tid];
        float loss = 0.f;
        if (m >= 0) {
            float sc[5];
            #pragma unroll
            for (int q = 0; q < 5; q++)
                sc[q] = red[0][tid * 5 + q] + red[1][tid * 5 + q] +
                        red[2][tid * 5 + q] + red[3][tid * 5 + q];
            const float neg_mean = (sc[1] + sc[2] + sc[3] + sc[4]) * 0.25f;
            const float x = neg_mean - sc[0];
            const float sig = 1.0f / (1.0f + expf(-x));  // -inf -> 0, ref-compatible
            loss = -logf(sig + 1e-12f);
        }
        lsum[tid] = loss;
    }
    __syncthreads();
    if (tid == 0) {
        float blk = 0.f;
        #pragma unroll
        for (int i = 0; i < T; i++) blk += lsum[i];
        atomicAdd(out, blk * invB);
    }
}

extern "C" void kernel_launch(void* const* d_in, const int* in_sizes, int n_in,
                              void* d_out, int out_size)
{
    const float* mol_emb         = (const float*)d_in[0];
    const float* entity_emb      = (const float*)d_in[1];
    const float* relation_emb    = (const float*)d_in[2];
    const float* relation_matrix = (const float*)d_in[3];
    const int*   tail_ids        = (const int*)d_in[4];
    const int*   rel_ids         = (const int*)d_in[5];
    const int*   neg_indices     = (const int*)d_in[6];
    float* out = (float*)d_out;

    const int B = in_sizes[0] / D;                 // 512
    int n_rel = in_sizes[2] / D;                   // 64
    if (n_rel > MAX_REL) n_rel = MAX_REL;
    int M = in_sizes[5];                           // 8192
    if (M > MAX_M) M = MAX_M;
    const int n_per_b = M / B;                     // 16

    const int NB   = M / T + n_rel;                // padded tile upper bound
    const int npad = NB * T;

    kg_prologue_kernel<<<1, 1024>>>(rel_ids, out, M, n_rel, npad);
    kg_score_kernel<<<NB, 128>>>(mol_emb, entity_emb, relation_emb,
                                 relation_matrix, tail_ids, rel_ids,
                                 neg_indices, out, n_per_b, 1.0f / (float)B);
}

// round 13
// speedup vs baseline: 1.3655x; 1.2686x over previous
#include <cuda_runtime.h>
#include <math.h>

#define D        128
#define K_NEG    4
#define T        8            // same-relation triples per score block
#define NVEC     (5 * T)      // 40 u-vectors per block
#define THREADS  256          // 8 warps = 8 vec-groups of 5 vectors
#define MAX_M    16384
#define MAX_REL  256
#define NPAD_MAX (MAX_M + MAX_REL * T)

// packed f32x2 FMA and unpack
#define FMA_F32X2(d, a, b, c) \
    asm("fma.rn.f32x2 %0, %1, %2, %3;" : "=l"(d) : "l"(a), "l"(b), "l"(c))
#define UNPACK_F32X2(lo, hi, in) \
    asm("mov.b64 {%0, %1}, %2;" : "=f"(lo), "=f"(hi) : "l"(in))

// dynamic smem layout (bytes)
#define SMEM_R   0                         // Rs: 32 c4-blocks x 128 rows x float4 = 64 KB
#define SMEM_U   (SMEM_R + D * D * 4)      // u: 40 x 128 f32 = 20 KB
#define SMEM_E   (SMEM_U + NVEC * D * 4)   // evec: 128 f32
#define SMEM_SC  (SMEM_E + D * 4)          // per-vec scores: 40 f32
#define SMEM_SZ  (SMEM_SC + NVEC * 4)      // = 86,848 B

// ---- allocation-free scratch ----
__device__ int g_order[NPAD_MAX];

// K0: fused prologue, ONE block: zero out[0], smem histogram, warp-parallel
// padded exclusive scan, scatter + pad-fill + tail poison.
__global__ void __launch_bounds__(1024) kg_prologue_kernel(
    const int* __restrict__ rel_ids, float* __restrict__ out,
    int M, int n_rel, int npad)
{
    __shared__ int scnt[MAX_REL];
    __shared__ int soff[MAX_REL];
    __shared__ int spos[MAX_REL];
    __shared__ int stotal;
    const int tid = threadIdx.x;

    if (tid == 0) out[0] = 0.0f;
    for (int i = tid; i < n_rel; i += 1024) { scnt[i] = 0; spos[i] = 0; }
    __syncthreads();

    for (int m = tid; m < M; m += 1024) atomicAdd(&scnt[rel_ids[m]], 1);
    __syncthreads();

    if (n_rel <= 64) {
        if (tid < 32) {
            const int lane = tid;
            const int p0 = (lane < n_rel)
                ? ((scnt[lane] + T - 1) / T) * T : 0;
            const int p1 = (lane + 32 < n_rel)
                ? ((scnt[lane + 32] + T - 1) / T) * T : 0;
            int c0 = p0, c1 = p1;
            #pragma unroll
            for (int off = 1; off < 32; off <<= 1) {
                int n0 = __shfl_up_sync(0xFFFFFFFFu, c0, off);
                int n1 = __shfl_up_sync(0xFFFFFFFFu, c1, off);
                if (lane >= off) { c0 += n0; c1 += n1; }
            }
            const int tot0 = __shfl_sync(0xFFFFFFFFu, c0, 31);
            const int tot1 = __shfl_sync(0xFFFFFFFFu, c1, 31);
            if (lane < n_rel) soff[lane] = c0 - p0;
            if (lane + 32 < n_rel) soff[lane + 32] = tot0 + c1 - p1;
            if (lane == 31) stotal = tot0 + tot1;
        }
    } else if (tid == 0) {
        int acc = 0;
        for (int r = 0; r < n_rel; r++) {
            soff[r] = acc;
            acc += ((scnt[r] + T - 1) / T) * T;
        }
        stotal = acc;
    }
    __syncthreads();

    for (int m = tid; m < M; m += 1024) {
        const int r = rel_ids[m];
        const int p = atomicAdd(&spos[r], 1);
        g_order[soff[r] + p] = m;
    }
    {
        const int r = tid / T, s = tid % T;
        for (int rr = r; rr < n_rel; rr += 1024 / T) {
            const int cnt = scnt[rr];
            const int pad = ((cnt + T - 1) / T) * T;
            const int slot = cnt + s;
            if (slot < pad) g_order[soff[rr] + slot] = -1;
        }
    }
    for (int i = stotal + tid; i < npad; i += 1024) g_order[i] = -1;
}

// K1: score with 2-D register tiling.
// Block = one T-slot same-relation tile, 256 threads.
// warp = vec-group (5 vectors); lane l owns rows {l, 32+l, 64+l, 96+l}.
// R staged in smem as Rs[c4][row] (float4-transposed) -> lane-consecutive
// conflict-free LDS; u reads are warp-uniform broadcasts.
// Each thread accumulates 4 rows x 5 vecs complete dots (packed f32x2).
__global__ void __launch_bounds__(THREADS, 2) kg_score_kernel(
    const float* __restrict__ mol_emb,        // [B, D]
    const float* __restrict__ entity_emb,     // [N_ENT, D]
    const float* __restrict__ relation_emb,   // [N_REL, D]
    const float* __restrict__ relation_matrix,// [N_REL, D, D]
    const int*   __restrict__ tail_ids,       // [M]
    const int*   __restrict__ rel_ids,        // [M]
    const int*   __restrict__ neg_indices,    // [M, K]
    float* __restrict__ out,
    int n_per_b, float invB)
{
    extern __shared__ __align__(16) char smem[];
    float4* Rs = reinterpret_cast<float4*>(smem + SMEM_R);
    float*  uv = reinterpret_cast<float*>(smem + SMEM_U);
    float*  ev = reinterpret_cast<float*>(smem + SMEM_E);
    float*  sc = reinterpret_cast<float*>(smem + SMEM_SC);

    __shared__ int   sm_m[T];
    __shared__ int   sm_b[T];
    __shared__ int   sm_row[NVEC];
    __shared__ int   sm_rel;
    __shared__ float lsum[T];

    const int tid = threadIdx.x;

    if (tid < T) {
        const int m = g_order[blockIdx.x * T + tid];
        sm_m[tid] = m;
        sm_b[tid] = (m >= 0) ? (m / n_per_b) : -1;
    }
    __syncthreads();

    if (tid < NVEC) {
        const int i = tid / 5, q = tid - i * 5;
        const int m = sm_m[i];
        int row = -1;
        if (m >= 0)
            row = (q == 0) ? tail_ids[m]
                           : tail_ids[neg_indices[m * K_NEG + (q - 1)]];
        sm_row[tid] = row;
        if (tid == 0) {
            int r = -1;
            #pragma unroll
            for (int j = 0; j < T; j++)
                if (r < 0 && sm_m[j] >= 0) r = rel_ids[sm_m[j]];
            sm_rel = r;
        }
    }
    __syncthreads();

    const int r_id = sm_rel;
    if (r_id < 0) return;            // dead padding block (uniform exit)

    // ---- stage R (64 KB) transposed at float4 granularity: Rs[c4*D+row] ----
    // consecutive tids -> consecutive rows, same c4: STS contiguous (conflict-
    // free); LDG lanes stride 512B (one-time sector waste, acceptable).
    {
        const float4* Rg = reinterpret_cast<const float4*>(
            relation_matrix + (size_t)r_id * D * D);
        #pragma unroll 4
        for (int idx = tid; idx < D * (D / 4); idx += THREADS) {
            const int c4 = idx >> 7;          // 0..31
            const int row = idx & 127;
            Rs[c4 * D + row] = Rg[row * (D / 4) + c4];
        }
    }
    if (tid < D) ev[tid] = relation_emb[(size_t)r_id * D + tid];
    // ---- stage u vectors: 2 vectors at a time across 256 threads ----
    {
        const int c = tid & 127;
        const int jo = tid >> 7;              // 0 or 1
        for (int j = jo; j < NVEC; j += 2) {
            const int i = j / 5;
            const int b = sm_b[i];
            const float h = (b >= 0) ? mol_emb[(size_t)b * D + c] : 0.f;
            const int row = sm_row[j];
            uv[j * D + c] =
                (row >= 0) ? (h - entity_emb[(size_t)row * D + c]) : 0.f;
        }
    }
    __syncthreads();

    // ---- mainloop: 4 rows x 5 vecs per thread, packed f32x2 ----
    const int l  = tid & 31;
    const int vg = tid >> 5;                  // 0..7
    const ulonglong2* Rs2 = reinterpret_cast<const ulonglong2*>(smem + SMEM_R);
    const ulonglong2* u2  = reinterpret_cast<const ulonglong2*>(smem + SMEM_U);

    unsigned long long acc[4][5];
    #pragma unroll
    for (int i = 0; i < 4; i++)
        #pragma unroll
        for (int q = 0; q < 5; q++) acc[i][q] = 0ull;

    #pragma unroll 2
    for (int c4 = 0; c4 < D / 4; c4++) {
        const ulonglong2 r0 = Rs2[c4 * D + l];
        const ulonglong2 r1 = Rs2[c4 * D + 32 + l];
        const ulonglong2 r2 = Rs2[c4 * D + 64 + l];
        const ulonglong2 r3 = Rs2[c4 * D + 96 + l];
        #pragma unroll
        for (int q = 0; q < 5; q++) {
            const ulonglong2 v = u2[(5 * vg + q) * (D / 4) + c4]; // broadcast
            FMA_F32X2(acc[0][q], r0.x, v.x, acc[0][q]);
            FMA_F32X2(acc[0][q], r0.y, v.y, acc[0][q]);
            FMA_F32X2(acc[1][q], r1.x, v.x, acc[1][q]);
            FMA_F32X2(acc[1][q], r1.y, v.y, acc[1][q]);
            FMA_F32X2(acc[2][q], r2.x, v.x, acc[2][q]);
            FMA_F32X2(acc[2][q], r2.y, v.y, acc[2][q]);
            FMA_F32X2(acc[3][q], r3.x, v.x, acc[3][q]);
            FMA_F32X2(acc[3][q], r3.y, v.y, acc[3][q]);
        }
    }

    // ---- epilogue: complete dots in-register; shuffle-reduce per vec ----
    const float e0 = ev[l];
    const float e1 = ev[32 + l];
    const float e2 = ev[64 + l];
    const float e3 = ev[96 + l];
    #pragma unroll
    for (int q = 0; q < 5; q++) {
        float lo, hi, d, s = 0.f;
        UNPACK_F32X2(lo, hi, acc[0][q]); d = (lo + hi) + e0; s = fmaf(d, d, s);
        UNPACK_F32X2(lo, hi, acc[1][q]); d = (lo + hi) + e1; s = fmaf(d, d, s);
        UNPACK_F32X2(lo, hi, acc[2][q]); d = (lo + hi) + e2; s = fmaf(d, d, s);
        UNPACK_F32X2(lo, hi, acc[3][q]); d = (lo + hi) + e3; s = fmaf(d, d, s);
        #pragma unroll
        for (int off = 16; off > 0; off >>= 1)
            s += __shfl_down_sync(0xFFFFFFFFu, s, off);
        if (l == 0) sc[5 * vg + q] = s;      // vec (5*vg+q) owned by warp vg
    }
    __syncthreads();

    if (tid < T) {
        const int m = sm_m[tid];
        float loss = 0.f;
        if (m >= 0) {
            const float pos = sc[5 * tid];
            const float neg_mean = (sc[5 * tid + 1] + sc[5 * tid + 2] +
                                    sc[5 * tid + 3] + sc[5 * tid + 4]) * 0.25f;
            const float x = neg_mean - pos;
            const float sig = 1.0f / (1.0f + expf(-x)); // -inf -> 0, ref-compatible
            loss = -logf(sig + 1e-12f);
        }
        lsum[tid] = loss;
    }
    __syncthreads();
    if (tid == 0) {
        float blk = 0.f;
        #pragma unroll
        for (int i = 0; i < T; i++) blk += lsum[i];
        atomicAdd(out, blk * invB);
    }
}

extern "C" void kernel_launch(void* const* d_in, const int* in_sizes, int n_in,
                              void* d_out, int out_size)
{
    const float* mol_emb         = (const float*)d_in[0];
    const float* entity_emb      = (const float*)d_in[1];
    const float* relation_emb    = (const float*)d_in[2];
    const float* relation_matrix = (const float*)d_in[3];
    const int*   tail_ids        = (const int*)d_in[4];
    const int*   rel_ids         = (const int*)d_in[5];
    const int*   neg_indices     = (const int*)d_in[6];
    float* out = (float*)d_out;

    const int B = in_sizes[0] / D;                 // 512
    int n_rel = in_sizes[2] / D;                   // 64
    if (n_rel > MAX_REL) n_rel = MAX_REL;
    int M = in_sizes[5];                           // 8192
    if (M > MAX_M) M = MAX_M;
    const int n_per_b = M / B;                     // 16

    const int NB   = M / T + n_rel;                // 1088 padded tiles
    const int npad = NB * T;

    // opt-in to >48KB dynamic smem (idempotent; immediate, not captured)
    cudaFuncSetAttribute(kg_score_kernel,
                         cudaFuncAttributeMaxDynamicSharedMemorySize, SMEM_SZ);

    kg_prologue_kernel<<<1, 1024>>>(rel_ids, out, M, n_rel, npad);
    kg_score_kernel<<<NB, THREADS, SMEM_SZ>>>(
        mol_emb, entity_emb, relation_emb, relation_matrix,
        tail_ids, rel_ids, neg_indices, out, n_per_b, 1.0f / (float)B);
}